// round 10
// baseline (speedup 1.0000x reference)
#include <cuda_runtime.h>
#include <math.h>

#define BB    16
#define SIN   400
#define SOUT  100
#define HH    256
#define EE    128
#define VV    50000
#define G4    1024
#define H2    512
#define G8    2048
#define NROW  (BB*SOUT)
#define EPSF  1e-10f

typedef unsigned long long ull;

// ---------------- static device scratch ----------------
__device__ float4 g_WtEf4[256*256];     // enc Whh fwd: [k][cell] -> (i,f,g,o)
__device__ float4 g_WtEb4[256*256];
__device__ float4 g_WtD4 [512*512];     // dec Whh
__device__ float  g_xgf[BB*SIN*G4];
__device__ float  g_xgb[BB*SIN*G4];
__device__ float  g_xgd[BB*SOUT*G8];
__device__ float  g_ansemb[BB*SOUT*EE];
__device__ float  g_xb[BB*SIN*H2];
__device__ float  g_h0[BB*H2];
__device__ float  g_c0[BB*H2];
__device__ float  g_feat[NROW*G4];      // [row][0:512]=dec_out, [512:1024]=context
__device__ float  g_attn[NROW*SIN];
__device__ float  g_pgen[NROW];
__device__ float  g_rmax[NROW];
__device__ float  g_rscale[NROW];

__device__ __forceinline__ float sigm(float x){ return 1.f/(1.f+__expf(-x)); }
__device__ __forceinline__ float tanh_(float x){ return 2.f/(1.f+__expf(-2.f*x)) - 1.f; }
__device__ __forceinline__ ull dup2(float v){
    unsigned int u = __float_as_uint(v);
    return ((ull)u << 32) | (ull)u;
}
__device__ __forceinline__ void fma2(ull &d, ull a, ull b){
    asm("fma.rn.f32x2 %0, %1, %2, %0;" : "+l"(d) : "l"(a), "l"(b));
}

// ---------------- weight transposes (Whh only) ----------------
__global__ void k_transpose(const float* __restrict__ ef, const float* __restrict__ eb,
                            const float* __restrict__ dw)
{
    int job = blockIdx.y;
    int idx = blockIdx.x*256 + threadIdx.x;
    if (job == 0) {
        if (idx < 256*256){ int k = idx>>8, j = idx&255;
            g_WtEf4[idx] = make_float4(ef[j*256+k], ef[(256+j)*256+k], ef[(512+j)*256+k], ef[(768+j)*256+k]); }
    } else if (job == 1) {
        if (idx < 256*256){ int k = idx>>8, j = idx&255;
            g_WtEb4[idx] = make_float4(eb[j*256+k], eb[(256+j)*256+k], eb[(512+j)*256+k], eb[(768+j)*256+k]); }
    } else {
        if (idx < 512*512){ int k = idx>>9, c = idx&511;
            g_WtD4[idx] = make_float4(dw[c*512+k], dw[(512+c)*512+k], dw[(1024+c)*512+k], dw[(1536+c)*512+k]); }
    }
}

// ---------------- input-gate GEMM: out[row][g] = emb[tok(row)] . W[g] + bias[g] ----------------
// Tiled 128x128, K=128 (4 chunks of 32), 8x8 microtile per thread.
__global__ void __launch_bounds__(256) k_xg_gemm(
    const float* __restrict__ emb, const float* __restrict__ W,
    const float* __restrict__ bias, const int* __restrict__ toks,
    int Tlen, int rev, int M, float* __restrict__ out)
{
    __shared__ float As[32][128];
    __shared__ float Bs[32][128];
    int n0 = blockIdx.x*128, m0 = blockIdx.y*128;
    int tid = threadIdx.x;
    int tx = tid & 15, ty = tid >> 4;
    int lr = tid >> 1;            // row within tile for loads (0..127)
    int lp = (tid & 1) * 4;       // float4 group within chunk (0 or 4)
    size_t N = (size_t)gridDim.x * 128;

    // resolve token for this load row once
    int tokA = 0;
    int gmA = m0 + lr;
    if (gmA < M){
        int b = gmA / Tlen, t = gmA % Tlen;
        int tt = rev ? (Tlen-1-t) : t;
        tokA = toks[b*Tlen + tt];
    }
    int gnB = n0 + lr;

    float acc[8][8];
    #pragma unroll
    for (int i=0;i<8;i++)
        #pragma unroll
        for (int j=0;j<8;j++) acc[i][j] = 0.f;

    #pragma unroll
    for (int kc = 0; kc < 4; kc++){
        int f4base = kc*8;
        #pragma unroll
        for (int j=0;j<4;j++){
            int f4 = lp + j;                  // 0..7 within chunk
            float4 a = make_float4(0.f,0.f,0.f,0.f);
            if (gmA < M) a = ((const float4*)emb)[(size_t)tokA*32 + f4base + f4];
            int kk = f4*4;
            As[kk+0][lr]=a.x; As[kk+1][lr]=a.y; As[kk+2][lr]=a.z; As[kk+3][lr]=a.w;
            float4 bv = ((const float4*)W)[((size_t)gnB*128)/4 + f4base + f4];
            Bs[kk+0][lr]=bv.x; Bs[kk+1][lr]=bv.y; Bs[kk+2][lr]=bv.z; Bs[kk+3][lr]=bv.w;
        }
        __syncthreads();
        #pragma unroll
        for (int k=0;k<32;k++){
            float4 a0 = *(const float4*)&As[k][ty*8];
            float4 a1 = *(const float4*)&As[k][ty*8+4];
            float4 b0 = *(const float4*)&Bs[k][tx*8];
            float4 b1 = *(const float4*)&Bs[k][tx*8+4];
            float av[8] = {a0.x,a0.y,a0.z,a0.w,a1.x,a1.y,a1.z,a1.w};
            float bw[8] = {b0.x,b0.y,b0.z,b0.w,b1.x,b1.y,b1.z,b1.w};
            #pragma unroll
            for (int i=0;i<8;i++)
                #pragma unroll
                for (int j=0;j<8;j++) acc[i][j] = fmaf(av[i], bw[j], acc[i][j]);
        }
        __syncthreads();
    }

    #pragma unroll
    for (int i=0;i<8;i++){
        int gm = m0 + ty*8 + i;
        if (gm < M){
            #pragma unroll
            for (int j=0;j<8;j++){
                int gn = n0 + tx*8 + j;
                out[(size_t)gm*N + gn] = acc[i][j] + bias[gn];
            }
        }
    }
}

// ---------------- ans embedding copy ----------------
__global__ void k_ansemb(const int* __restrict__ ans, const float* __restrict__ emb)
{
    int row = blockIdx.x, v = threadIdx.x;   // 32 threads
    int tok = ans[row];
    ((float4*)g_ansemb)[(size_t)row*32 + v] = ((const float4*)emb)[(size_t)tok*32 + v];
}

// ---------------- encoder BiLSTM: block owns (dir, b) ----------------
__global__ void __launch_bounds__(256) k_enc()
{
    int dir = blockIdx.x >> 4, b = blockIdx.x & 15;
    const float4* __restrict__ Wt = dir ? g_WtEb4 : g_WtEf4;
    const float* xg = (dir ? g_xgb : g_xgf) + (size_t)b*SIN*G4;
    __shared__ float hs[256];
    int j = threadIdx.x;
    float c = 0.f, hn = 0.f;
    hs[j] = 0.f;
    __syncthreads();
    for (int t=0;t<SIN;t++){
        const float* xr = xg + (size_t)t*G4;
        float gi=xr[j], gf=xr[256+j], gg=xr[512+j], go=xr[768+j];
        #pragma unroll 8
        for (int k=0;k<256;k++){
            float hk = hs[k];
            float4 w = Wt[k*256 + j];
            gi = fmaf(w.x, hk, gi); gf = fmaf(w.y, hk, gf);
            gg = fmaf(w.z, hk, gg); go = fmaf(w.w, hk, go);
        }
        float cn = sigm(gf)*c + sigm(gi)*tanh_(gg);
        hn = sigm(go)*tanh_(cn);
        c = cn;
        __syncthreads();
        hs[j] = hn;
        int tp = dir ? (SIN-1-t) : t;
        g_xb[(size_t)(b*SIN + tp)*H2 + dir*256 + j] = hn;
        __syncthreads();
    }
    g_h0[b*H2 + dir*256 + j] = hn;
    g_c0[b*H2 + dir*256 + j] = c;
}

// ---------------- decoder LSTM (hidden 512) ----------------
__global__ void __launch_bounds__(256) k_dec()
{
    int b = blockIdx.x, j = threadIdx.x;
    __shared__ float hs[512];
    float c0 = g_c0[b*H2 + j], c1 = g_c0[b*H2 + 256 + j];
    hs[j]     = g_h0[b*H2 + j];
    hs[256+j] = g_h0[b*H2 + 256 + j];
    __syncthreads();
    for (int t=0;t<SOUT;t++){
        const float* xr = g_xgd + (size_t)(b*SOUT + t)*G8;
        float ai=xr[j],     af=xr[512+j],  ag=xr[1024+j], ao=xr[1536+j];
        float bi=xr[256+j], bf=xr[768+j],  bg=xr[1280+j], bo=xr[1792+j];
        #pragma unroll 4
        for (int k=0;k<512;k++){
            float hk = hs[k];
            float4 w0 = g_WtD4[k*512 + j];
            float4 w1 = g_WtD4[k*512 + 256 + j];
            ai=fmaf(w0.x,hk,ai); af=fmaf(w0.y,hk,af); ag=fmaf(w0.z,hk,ag); ao=fmaf(w0.w,hk,ao);
            bi=fmaf(w1.x,hk,bi); bf=fmaf(w1.y,hk,bf); bg=fmaf(w1.z,hk,bg); bo=fmaf(w1.w,hk,bo);
        }
        float cn0 = sigm(af)*c0 + sigm(ai)*tanh_(ag);
        float h0n = sigm(ao)*tanh_(cn0);
        float cn1 = sigm(bf)*c1 + sigm(bi)*tanh_(bg);
        float h1n = sigm(bo)*tanh_(cn1);
        c0 = cn0; c1 = cn1;
        __syncthreads();
        hs[j] = h0n; hs[256+j] = h1n;
        float* fr = g_feat + (size_t)(b*SOUT + t)*G4;
        fr[j] = h0n; fr[256+j] = h1n;
        __syncthreads();
    }
}

// ---------------- attention + context + pgen ----------------
__global__ void __launch_bounds__(256) k_attn(const float* __restrict__ wpg, const float* __restrict__ bpg)
{
    int row = blockIdx.x;
    int b = row / SOUT;
    __shared__ float ds[512];
    __shared__ float ctx[512];
    __shared__ float sc[SIN];
    __shared__ float red[256];
    int tid = threadIdx.x, lane = tid & 31, wid = tid >> 5;
    float* feat = g_feat + (size_t)row*G4;
    ds[tid] = feat[tid]; ds[256+tid] = feat[256+tid];
    __syncthreads();

    // scores: warp per source position
    const float4* ds4 = (const float4*)ds;
    for (int s = wid; s < SIN; s += 8){
        const float4* xr = (const float4*)(g_xb + (size_t)(b*SIN + s)*H2);
        float acc = 0.f;
        #pragma unroll
        for (int i=0;i<4;i++){
            float4 a = xr[lane + i*32];
            float4 d = ds4[lane + i*32];
            acc += a.x*d.x + a.y*d.y + a.z*d.z + a.w*d.w;
        }
        #pragma unroll
        for (int o=16;o>0;o>>=1) acc += __shfl_xor_sync(0xffffffffu, acc, o);
        if (lane == 0) sc[s] = acc;
    }
    __syncthreads();

    // softmax over 400
    float m = -1e30f;
    for (int s = tid; s < SIN; s += 256) m = fmaxf(m, sc[s]);
    red[tid] = m; __syncthreads();
    for (int st=128; st>0; st>>=1){ if (tid < st) red[tid] = fmaxf(red[tid], red[tid+st]); __syncthreads(); }
    m = red[0]; __syncthreads();
    float ssum = 0.f;
    for (int s = tid; s < SIN; s += 256) ssum += __expf(sc[s] - m);
    red[tid] = ssum; __syncthreads();
    for (int st=128; st>0; st>>=1){ if (tid < st) red[tid] += red[tid+st]; __syncthreads(); }
    float inv = 1.f / red[0]; __syncthreads();
    for (int s = tid; s < SIN; s += 256){
        float a = __expf(sc[s] - m) * inv;
        sc[s] = a;
        g_attn[(size_t)row*SIN + s] = a;
    }
    __syncthreads();

    // context[d] = sum_s attn[s] * xb[s][d]
    #pragma unroll
    for (int h=0; h<2; h++){
        int d = tid + h*256;
        float acc = 0.f;
        const float* xp = g_xb + (size_t)b*SIN*H2 + d;
        for (int s=0; s<SIN; s++) acc = fmaf(sc[s], xp[(size_t)s*H2], acc);
        ctx[d] = acc;
        feat[512 + d] = acc;
    }
    __syncthreads();

    // pgen = sigmoid(Wpg . [ctx, dec_out, ans_emb] + b)
    float p = 0.f;
    #pragma unroll
    for (int h=0; h<2; h++){
        int i = tid + h*256;
        p += wpg[i]*ctx[i] + wpg[512+i]*ds[i];
    }
    if (tid < 128) p += wpg[1024+tid] * g_ansemb[(size_t)row*EE + tid];
    red[tid] = p; __syncthreads();
    for (int st=128; st>0; st>>=1){ if (tid < st) red[tid] += red[tid+st]; __syncthreads(); }
    if (tid == 0) g_pgen[row] = sigm(red[0] + bpg[0]);
}

// ---------------- projection GEMM: out = feat @ W_pro^T + b_pro (f32x2) ----------------
__global__ void __launch_bounds__(256) k_gemm(const float* __restrict__ Wp,
                                              const float* __restrict__ bp,
                                              float* __restrict__ out)
{
    __shared__ float As[16][128];
    __shared__ ull   Bs2[16][128];
    int m0 = blockIdx.y*128, n0 = blockIdx.x*128;
    int tid = threadIdx.x;
    int tx = tid & 15, ty = tid >> 4;
    int lm = tid >> 2;
    int lk = (tid & 3) * 4;
    ull acc[4][8];
    #pragma unroll
    for (int p=0;p<4;p++)
        #pragma unroll
        for (int j=0;j<8;j++) acc[p][j] = 0ull;

    for (int kt = 0; kt < 64; kt++){
        int kb = kt*16;
        #pragma unroll
        for (int h=0; h<2; h++){
            int r = lm + h*64;
            int gm = m0 + r;
            float4 a4 = make_float4(0.f,0.f,0.f,0.f);
            if (gm < NROW) a4 = *(const float4*)(g_feat + (size_t)gm*G4 + kb + lk);
            As[lk+0][r]=a4.x; As[lk+1][r]=a4.y; As[lk+2][r]=a4.z; As[lk+3][r]=a4.w;
            int gn = n0 + r;
            float4 b4 = make_float4(0.f,0.f,0.f,0.f);
            if (gn < VV) b4 = *(const float4*)(Wp + (size_t)gn*G4 + kb + lk);
            Bs2[lk+0][r]=dup2(b4.x); Bs2[lk+1][r]=dup2(b4.y);
            Bs2[lk+2][r]=dup2(b4.z); Bs2[lk+3][r]=dup2(b4.w);
        }
        __syncthreads();
        #pragma unroll
        for (int k=0;k<16;k++){
            ulonglong2 la0 = *(const ulonglong2*)&As[k][ty*8];
            ulonglong2 la1 = *(const ulonglong2*)&As[k][ty*8+4];
            ulonglong2 lb0 = *(const ulonglong2*)&Bs2[k][tx*8];
            ulonglong2 lb1 = *(const ulonglong2*)&Bs2[k][tx*8+2];
            ulonglong2 lb2 = *(const ulonglong2*)&Bs2[k][tx*8+4];
            ulonglong2 lb3 = *(const ulonglong2*)&Bs2[k][tx*8+6];
            ull av[4] = {la0.x, la0.y, la1.x, la1.y};
            ull bv[8] = {lb0.x, lb0.y, lb1.x, lb1.y, lb2.x, lb2.y, lb3.x, lb3.y};
            #pragma unroll
            for (int j=0;j<8;j++){
                #pragma unroll
                for (int p=0;p<4;p++) fma2(acc[p][j], av[p], bv[j]);
            }
        }
        __syncthreads();
    }
    #pragma unroll
    for (int p=0;p<4;p++){
        int gm = m0 + ty*8 + p*2;
        #pragma unroll
        for (int j=0;j<8;j++){
            int gn = n0 + tx*8 + j;
            if (gn < VV){
                union { ull u; float2 f; } cv; cv.u = acc[p][j];
                float bb = bp[gn];
                if (gm < NROW)     out[(size_t)gm*VV + gn]     = cv.f.x + bb;
                if (gm+1 < NROW)   out[(size_t)(gm+1)*VV + gn] = cv.f.y + bb;
            }
        }
    }
}

// ---------------- row softmax stats ----------------
__global__ void __launch_bounds__(256) k_rowstats(const float* __restrict__ out)
{
    int row = blockIdx.x, tid = threadIdx.x;
    __shared__ float red[256];
    const float* r = out + (size_t)row*VV;
    float m = -1e30f;
    for (int i = tid; i < VV; i += 256) m = fmaxf(m, r[i]);
    red[tid] = m; __syncthreads();
    for (int st=128; st>0; st>>=1){ if (tid < st) red[tid] = fmaxf(red[tid], red[tid+st]); __syncthreads(); }
    m = red[0]; __syncthreads();
    float s = 0.f;
    for (int i = tid; i < VV; i += 256) s += __expf(r[i] - m);
    red[tid] = s; __syncthreads();
    for (int st=128; st>0; st>>=1){ if (tid < st) red[tid] += red[tid+st]; __syncthreads(); }
    if (tid == 0){
        g_rmax[row] = m;
        g_rscale[row] = g_pgen[row] / red[0];
    }
}

// ---------------- transform logits -> pgen*softmax + eps ----------------
__global__ void k_transform(float* __restrict__ out)
{
    int row = blockIdx.y;
    int p = blockIdx.x*256 + threadIdx.x;
    if (p >= VV/4) return;
    float m = g_rmax[row], sc = g_rscale[row];
    float4* o4 = (float4*)(out + (size_t)row*VV);
    float4 v = o4[p];
    v.x = sc*__expf(v.x - m) + EPSF;
    v.y = sc*__expf(v.y - m) + EPSF;
    v.z = sc*__expf(v.z - m) + EPSF;
    v.w = sc*__expf(v.w - m) + EPSF;
    o4[p] = v;
}

// ---------------- pointer scatter ----------------
__global__ void k_scatter(const int* __restrict__ x, float* __restrict__ out)
{
    int row = blockIdx.x, s = threadIdx.x;
    if (s >= SIN) return;
    int b = row / SOUT;
    float w = (1.f - g_pgen[row]) * g_attn[(size_t)row*SIN + s];
    atomicAdd(out + (size_t)row*VV + x[b*SIN + s], w);
}

// ---------------- final log ----------------
__global__ void k_log(float* __restrict__ out)
{
    int row = blockIdx.y;
    int p = blockIdx.x*256 + threadIdx.x;
    if (p >= VV/4) return;
    float4* o4 = (float4*)(out + (size_t)row*VV);
    float4 v = o4[p];
    v.x = logf(v.x); v.y = logf(v.y); v.z = logf(v.z); v.w = logf(v.w);
    o4[p] = v;
}

extern "C" void kernel_launch(void* const* d_in, const int* in_sizes, int n_in,
                              void* d_out, int out_size)
{
    const int*   x    = (const int*)  d_in[0];
    const int*   ans  = (const int*)  d_in[1];
    const float* emb  = (const float*)d_in[2];
    const float* wif  = (const float*)d_in[3];
    const float* ehf  = (const float*)d_in[4];
    const float* ebf  = (const float*)d_in[5];
    const float* wib  = (const float*)d_in[6];
    const float* ehb  = (const float*)d_in[7];
    const float* ebb  = (const float*)d_in[8];
    const float* wid_ = (const float*)d_in[9];
    const float* dwh  = (const float*)d_in[10];
    const float* db   = (const float*)d_in[11];
    const float* Wp   = (const float*)d_in[12];
    const float* bp   = (const float*)d_in[13];
    const float* wpg  = (const float*)d_in[14];
    const float* bpg  = (const float*)d_in[15];
    float* out = (float*)d_out;

    float* xgf; cudaGetSymbolAddress((void**)&xgf, g_xgf);
    float* xgb; cudaGetSymbolAddress((void**)&xgb, g_xgb);
    float* xgd; cudaGetSymbolAddress((void**)&xgd, g_xgd);

    k_transpose<<<dim3(1024,3), 256>>>(ehf, ehb, dwh);
    k_xg_gemm<<<dim3(8, 50), 256>>>(emb, wif, ebf, x, SIN, 0, BB*SIN, xgf);
    k_xg_gemm<<<dim3(8, 50), 256>>>(emb, wib, ebb, x, SIN, 1, BB*SIN, xgb);
    k_xg_gemm<<<dim3(16, 13), 256>>>(emb, wid_, db, ans, SOUT, 0, BB*SOUT, xgd);
    k_ansemb<<<NROW, 32>>>(ans, emb);
    k_enc<<<32, 256>>>();
    k_dec<<<BB, 256>>>();
    k_attn<<<NROW, 256>>>(wpg, bpg);
    k_gemm<<<dim3((VV+127)/128, (NROW+127)/128), 256>>>(Wp, bp, out);
    k_rowstats<<<NROW, 256>>>(out);
    k_transform<<<dim3((VV/4+255)/256, NROW), 256>>>(out);
    k_scatter<<<NROW, 512>>>(x, out);
    k_log<<<dim3((VV/4+255)/256, NROW), 256>>>(out);
}

// round 11
// speedup vs baseline: 1.3430x; 1.3430x over previous
#include <cuda_runtime.h>
#include <math.h>

#define BB    16
#define SIN   400
#define SOUT  100
#define HH    256
#define EE    128
#define VV    50000
#define G4    1024
#define H2    512
#define G8    2048
#define NROW  (BB*SOUT)
#define EPSF  1e-10f

typedef unsigned long long ull;

// ---------------- static device scratch ----------------
__device__ float4 g_WtEf4[256*256];     // enc Whh fwd: [k][cell] -> (i,f,g,o)
__device__ float4 g_WtEb4[256*256];
__device__ float4 g_WtD4 [512*512];     // dec Whh
__device__ float  g_xgf[BB*SIN*G4];
__device__ float  g_xgb[BB*SIN*G4];
__device__ float  g_xgd[BB*SOUT*G8];
__device__ float  g_ansemb[BB*SOUT*EE];
__device__ float  g_xb[BB*SIN*H2];
__device__ float  g_h0[BB*H2];
__device__ float  g_c0[BB*H2];
__device__ float  g_feat[NROW*G4];      // [row][0:512]=dec_out, [512:1024]=context
__device__ float  g_attn[NROW*SIN];
__device__ float  g_pgen[NROW];
__device__ float  g_rmax[NROW];
__device__ float  g_rscale[NROW];

__device__ __forceinline__ float sigm(float x){ return 1.f/(1.f+__expf(-x)); }
__device__ __forceinline__ float tanh_(float x){ return 2.f/(1.f+__expf(-2.f*x)) - 1.f; }
__device__ __forceinline__ ull dup2(float v){
    unsigned int u = __float_as_uint(v);
    return ((ull)u << 32) | (ull)u;
}
__device__ __forceinline__ void fma2(ull &d, ull a, ull b){
    asm("fma.rn.f32x2 %0, %1, %2, %0;" : "+l"(d) : "l"(a), "l"(b));
}

// ---------------- weight transposes (Whh only) ----------------
__global__ void k_transpose(const float* __restrict__ ef, const float* __restrict__ eb,
                            const float* __restrict__ dw)
{
    int job = blockIdx.y;
    int idx = blockIdx.x*256 + threadIdx.x;
    if (job == 0) {
        if (idx < 256*256){ int k = idx>>8, j = idx&255;
            g_WtEf4[idx] = make_float4(ef[j*256+k], ef[(256+j)*256+k], ef[(512+j)*256+k], ef[(768+j)*256+k]); }
    } else if (job == 1) {
        if (idx < 256*256){ int k = idx>>8, j = idx&255;
            g_WtEb4[idx] = make_float4(eb[j*256+k], eb[(256+j)*256+k], eb[(512+j)*256+k], eb[(768+j)*256+k]); }
    } else {
        if (idx < 512*512){ int k = idx>>9, c = idx&511;
            g_WtD4[idx] = make_float4(dw[c*512+k], dw[(512+c)*512+k], dw[(1024+c)*512+k], dw[(1536+c)*512+k]); }
    }
}

// ---------------- input-gate GEMM: out[row][g] = emb[tok(row)] . W[g] + bias[g] ----------------
__global__ void __launch_bounds__(256) k_xg_gemm(
    const float* __restrict__ emb, const float* __restrict__ W,
    const float* __restrict__ bias, const int* __restrict__ toks,
    int Tlen, int rev, int M, float* __restrict__ out)
{
    __shared__ float As[32][128];
    __shared__ float Bs[32][128];
    int n0 = blockIdx.x*128, m0 = blockIdx.y*128;
    int tid = threadIdx.x;
    int tx = tid & 15, ty = tid >> 4;
    int lr = tid >> 1;
    int lp = (tid & 1) * 4;
    size_t N = (size_t)gridDim.x * 128;

    int tokA = 0;
    int gmA = m0 + lr;
    if (gmA < M){
        int b = gmA / Tlen, t = gmA % Tlen;
        int tt = rev ? (Tlen-1-t) : t;
        tokA = toks[b*Tlen + tt];
    }
    int gnB = n0 + lr;

    float acc[8][8];
    #pragma unroll
    for (int i=0;i<8;i++)
        #pragma unroll
        for (int j=0;j<8;j++) acc[i][j] = 0.f;

    #pragma unroll
    for (int kc = 0; kc < 4; kc++){
        int f4base = kc*8;
        #pragma unroll
        for (int j=0;j<4;j++){
            int f4 = lp + j;
            float4 a = make_float4(0.f,0.f,0.f,0.f);
            if (gmA < M) a = ((const float4*)emb)[(size_t)tokA*32 + f4base + f4];
            int kk = f4*4;
            As[kk+0][lr]=a.x; As[kk+1][lr]=a.y; As[kk+2][lr]=a.z; As[kk+3][lr]=a.w;
            float4 bv = ((const float4*)W)[((size_t)gnB*128)/4 + f4base + f4];
            Bs[kk+0][lr]=bv.x; Bs[kk+1][lr]=bv.y; Bs[kk+2][lr]=bv.z; Bs[kk+3][lr]=bv.w;
        }
        __syncthreads();
        #pragma unroll
        for (int k=0;k<32;k++){
            float4 a0 = *(const float4*)&As[k][ty*8];
            float4 a1 = *(const float4*)&As[k][ty*8+4];
            float4 b0 = *(const float4*)&Bs[k][tx*8];
            float4 b1 = *(const float4*)&Bs[k][tx*8+4];
            float av[8] = {a0.x,a0.y,a0.z,a0.w,a1.x,a1.y,a1.z,a1.w};
            float bw[8] = {b0.x,b0.y,b0.z,b0.w,b1.x,b1.y,b1.z,b1.w};
            #pragma unroll
            for (int i=0;i<8;i++)
                #pragma unroll
                for (int j=0;j<8;j++) acc[i][j] = fmaf(av[i], bw[j], acc[i][j]);
        }
        __syncthreads();
    }

    #pragma unroll
    for (int i=0;i<8;i++){
        int gm = m0 + ty*8 + i;
        if (gm < M){
            #pragma unroll
            for (int j=0;j<8;j++){
                int gn = n0 + tx*8 + j;
                out[(size_t)gm*N + gn] = acc[i][j] + bias[gn];
            }
        }
    }
}

// ---------------- ans embedding copy ----------------
__global__ void k_ansemb(const int* __restrict__ ans, const float* __restrict__ emb)
{
    int row = blockIdx.x, v = threadIdx.x;
    int tok = ans[row];
    ((float4*)g_ansemb)[(size_t)row*32 + v] = ((const float4*)emb)[(size_t)tok*32 + v];
}

// ---------------- encoder BiLSTM: block owns (dir, b) ----------------
__global__ void __launch_bounds__(256) k_enc()
{
    int dir = blockIdx.x >> 4, b = blockIdx.x & 15;
    const float4* __restrict__ Wt = dir ? g_WtEb4 : g_WtEf4;
    const float* xg = (dir ? g_xgb : g_xgf) + (size_t)b*SIN*G4;
    __shared__ float hs[256];
    int j = threadIdx.x;
    float c = 0.f, hn = 0.f;
    hs[j] = 0.f;
    __syncthreads();
    for (int t=0;t<SIN;t++){
        const float* xr = xg + (size_t)t*G4;
        float gi=xr[j], gf=xr[256+j], gg=xr[512+j], go=xr[768+j];
        #pragma unroll 8
        for (int k=0;k<256;k++){
            float hk = hs[k];
            float4 w = Wt[k*256 + j];
            gi = fmaf(w.x, hk, gi); gf = fmaf(w.y, hk, gf);
            gg = fmaf(w.z, hk, gg); go = fmaf(w.w, hk, go);
        }
        float cn = sigm(gf)*c + sigm(gi)*tanh_(gg);
        hn = sigm(go)*tanh_(cn);
        c = cn;
        __syncthreads();
        hs[j] = hn;
        int tp = dir ? (SIN-1-t) : t;
        g_xb[(size_t)(b*SIN + tp)*H2 + dir*256 + j] = hn;
        __syncthreads();
    }
    g_h0[b*H2 + dir*256 + j] = hn;
    g_c0[b*H2 + dir*256 + j] = c;
}

// ---------------- decoder LSTM (hidden 512) ----------------
__global__ void __launch_bounds__(256) k_dec()
{
    int b = blockIdx.x, j = threadIdx.x;
    __shared__ float hs[512];
    float c0 = g_c0[b*H2 + j], c1 = g_c0[b*H2 + 256 + j];
    hs[j]     = g_h0[b*H2 + j];
    hs[256+j] = g_h0[b*H2 + 256 + j];
    __syncthreads();
    for (int t=0;t<SOUT;t++){
        const float* xr = g_xgd + (size_t)(b*SOUT + t)*G8;
        float ai=xr[j],     af=xr[512+j],  ag=xr[1024+j], ao=xr[1536+j];
        float bi=xr[256+j], bf=xr[768+j],  bg=xr[1280+j], bo=xr[1792+j];
        #pragma unroll 4
        for (int k=0;k<512;k++){
            float hk = hs[k];
            float4 w0 = g_WtD4[k*512 + j];
            float4 w1 = g_WtD4[k*512 + 256 + j];
            ai=fmaf(w0.x,hk,ai); af=fmaf(w0.y,hk,af); ag=fmaf(w0.z,hk,ag); ao=fmaf(w0.w,hk,ao);
            bi=fmaf(w1.x,hk,bi); bf=fmaf(w1.y,hk,bf); bg=fmaf(w1.z,hk,bg); bo=fmaf(w1.w,hk,bo);
        }
        float cn0 = sigm(af)*c0 + sigm(ai)*tanh_(ag);
        float h0n = sigm(ao)*tanh_(cn0);
        float cn1 = sigm(bf)*c1 + sigm(bi)*tanh_(bg);
        float h1n = sigm(bo)*tanh_(cn1);
        c0 = cn0; c1 = cn1;
        __syncthreads();
        hs[j] = h0n; hs[256+j] = h1n;
        float* fr = g_feat + (size_t)(b*SOUT + t)*G4;
        fr[j] = h0n; fr[256+j] = h1n;
        __syncthreads();
    }
}

// ---------------- attention + context + pgen ----------------
__global__ void __launch_bounds__(256) k_attn(const float* __restrict__ wpg, const float* __restrict__ bpg)
{
    int row = blockIdx.x;
    int b = row / SOUT;
    __shared__ float ds[512];
    __shared__ float ctx[512];
    __shared__ float sc[SIN];
    __shared__ float red[256];
    int tid = threadIdx.x, lane = tid & 31, wid = tid >> 5;
    float* feat = g_feat + (size_t)row*G4;
    ds[tid] = feat[tid]; ds[256+tid] = feat[256+tid];
    __syncthreads();

    const float4* ds4 = (const float4*)ds;
    for (int s = wid; s < SIN; s += 8){
        const float4* xr = (const float4*)(g_xb + (size_t)(b*SIN + s)*H2);
        float acc = 0.f;
        #pragma unroll
        for (int i=0;i<4;i++){
            float4 a = xr[lane + i*32];
            float4 d = ds4[lane + i*32];
            acc += a.x*d.x + a.y*d.y + a.z*d.z + a.w*d.w;
        }
        #pragma unroll
        for (int o=16;o>0;o>>=1) acc += __shfl_xor_sync(0xffffffffu, acc, o);
        if (lane == 0) sc[s] = acc;
    }
    __syncthreads();

    float m = -1e30f;
    for (int s = tid; s < SIN; s += 256) m = fmaxf(m, sc[s]);
    red[tid] = m; __syncthreads();
    for (int st=128; st>0; st>>=1){ if (tid < st) red[tid] = fmaxf(red[tid], red[tid+st]); __syncthreads(); }
    m = red[0]; __syncthreads();
    float ssum = 0.f;
    for (int s = tid; s < SIN; s += 256) ssum += __expf(sc[s] - m);
    red[tid] = ssum; __syncthreads();
    for (int st=128; st>0; st>>=1){ if (tid < st) red[tid] += red[tid+st]; __syncthreads(); }
    float inv = 1.f / red[0]; __syncthreads();
    for (int s = tid; s < SIN; s += 256){
        float a = __expf(sc[s] - m) * inv;
        sc[s] = a;
        g_attn[(size_t)row*SIN + s] = a;
    }
    __syncthreads();

    #pragma unroll
    for (int h=0; h<2; h++){
        int d = tid + h*256;
        float acc = 0.f;
        const float* xp = g_xb + (size_t)b*SIN*H2 + d;
        for (int s=0; s<SIN; s++) acc = fmaf(sc[s], xp[(size_t)s*H2], acc);
        ctx[d] = acc;
        feat[512 + d] = acc;
    }
    __syncthreads();

    float p = 0.f;
    #pragma unroll
    for (int h=0; h<2; h++){
        int i = tid + h*256;
        p += wpg[i]*ctx[i] + wpg[512+i]*ds[i];
    }
    if (tid < 128) p += wpg[1024+tid] * g_ansemb[(size_t)row*EE + tid];
    red[tid] = p; __syncthreads();
    for (int st=128; st>0; st>>=1){ if (tid < st) red[tid] += red[tid+st]; __syncthreads(); }
    if (tid == 0) g_pgen[row] = sigm(red[0] + bpg[0]);
}

// ---------------- projection GEMM: out = feat @ W_pro^T + b_pro (f32x2) ----------------
// 128x128 tile, KB=16, double-buffered, conflict-free smem access.
// Thread (tx,ty): m = m0 + ty*8 + 2p (+1), p=0..3; n = n0 + 2*tx + 32*jj (+1), jj=0..3.
__global__ void __launch_bounds__(256) k_gemm(const float* __restrict__ Wp,
                                              const float* __restrict__ bp,
                                              float* __restrict__ out)
{
    __shared__ ull As2[2][16*64];    // [k][m-pair]  (low ull half = even m)
    __shared__ ull Bs2[2][16*128];   // [k][n] duplicated pairs
    int m0 = blockIdx.y*128, n0 = blockIdx.x*128;
    int tid = threadIdx.x;
    int tx = tid & 15, ty = tid >> 4;
    int lr = tid & 127;              // load row
    int lq = tid >> 7;               // 0/1 -> k-quarters {0,1} or {2,3}
    int gmA = m0 + lr;
    int gnB = n0 + lr;

    ull acc[4][8];
    #pragma unroll
    for (int p=0;p<4;p++)
        #pragma unroll
        for (int j=0;j<8;j++) acc[p][j] = 0ull;

    float4 pa0, pa1, pb0, pb1;
    // prologue load tile 0
    {
        int kb = 0;
        pa0 = make_float4(0.f,0.f,0.f,0.f); pa1 = pa0; pb0 = pa0; pb1 = pa0;
        if (gmA < NROW){
            pa0 = *(const float4*)(g_feat + (size_t)gmA*G4 + kb + lq*8);
            pa1 = *(const float4*)(g_feat + (size_t)gmA*G4 + kb + lq*8 + 4);
        }
        if (gnB < VV){
            pb0 = *(const float4*)(Wp + (size_t)gnB*G4 + kb + lq*8);
            pb1 = *(const float4*)(Wp + (size_t)gnB*G4 + kb + lq*8 + 4);
        }
    }
    {
        float* Af = (float*)As2[0];
        int r0 = lq*8;
        Af[(r0+0)*128+lr]=pa0.x; Af[(r0+1)*128+lr]=pa0.y; Af[(r0+2)*128+lr]=pa0.z; Af[(r0+3)*128+lr]=pa0.w;
        Af[(r0+4)*128+lr]=pa1.x; Af[(r0+5)*128+lr]=pa1.y; Af[(r0+6)*128+lr]=pa1.z; Af[(r0+7)*128+lr]=pa1.w;
        ull* Bf = Bs2[0];
        Bf[(r0+0)*128+lr]=dup2(pb0.x); Bf[(r0+1)*128+lr]=dup2(pb0.y);
        Bf[(r0+2)*128+lr]=dup2(pb0.z); Bf[(r0+3)*128+lr]=dup2(pb0.w);
        Bf[(r0+4)*128+lr]=dup2(pb1.x); Bf[(r0+5)*128+lr]=dup2(pb1.y);
        Bf[(r0+6)*128+lr]=dup2(pb1.z); Bf[(r0+7)*128+lr]=dup2(pb1.w);
    }
    __syncthreads();

    for (int kt = 0; kt < 64; kt++){
        int cur = kt & 1;
        // prefetch next tile into registers
        if (kt+1 < 64){
            int kb = (kt+1)*16;
            pa0 = make_float4(0.f,0.f,0.f,0.f); pa1 = pa0; pb0 = pa0; pb1 = pa0;
            if (gmA < NROW){
                pa0 = *(const float4*)(g_feat + (size_t)gmA*G4 + kb + lq*8);
                pa1 = *(const float4*)(g_feat + (size_t)gmA*G4 + kb + lq*8 + 4);
            }
            if (gnB < VV){
                pb0 = *(const float4*)(Wp + (size_t)gnB*G4 + kb + lq*8);
                pb1 = *(const float4*)(Wp + (size_t)gnB*G4 + kb + lq*8 + 4);
            }
        }
        // compute on current buffer
        const ulonglong2* Av = (const ulonglong2*)As2[cur];
        const ulonglong2* Bv = (const ulonglong2*)Bs2[cur];
        #pragma unroll
        for (int k=0;k<16;k++){
            ulonglong2 a01 = Av[k*32 + ty*2];
            ulonglong2 a23 = Av[k*32 + ty*2 + 1];
            ull av[4] = {a01.x, a01.y, a23.x, a23.y};
            #pragma unroll
            for (int jj=0;jj<4;jj++){
                ulonglong2 bv = Bv[k*64 + tx + 16*jj];
                #pragma unroll
                for (int p=0;p<4;p++){
                    fma2(acc[p][2*jj],   av[p], bv.x);
                    fma2(acc[p][2*jj+1], av[p], bv.y);
                }
            }
        }
        __syncthreads();
        if (kt+1 < 64){
            int nxt = (kt+1) & 1;
            float* Af = (float*)As2[nxt];
            int r0 = lq*8;
            Af[(r0+0)*128+lr]=pa0.x; Af[(r0+1)*128+lr]=pa0.y; Af[(r0+2)*128+lr]=pa0.z; Af[(r0+3)*128+lr]=pa0.w;
            Af[(r0+4)*128+lr]=pa1.x; Af[(r0+5)*128+lr]=pa1.y; Af[(r0+6)*128+lr]=pa1.z; Af[(r0+7)*128+lr]=pa1.w;
            ull* Bf = Bs2[nxt];
            Bf[(r0+0)*128+lr]=dup2(pb0.x); Bf[(r0+1)*128+lr]=dup2(pb0.y);
            Bf[(r0+2)*128+lr]=dup2(pb0.z); Bf[(r0+3)*128+lr]=dup2(pb0.w);
            Bf[(r0+4)*128+lr]=dup2(pb1.x); Bf[(r0+5)*128+lr]=dup2(pb1.y);
            Bf[(r0+6)*128+lr]=dup2(pb1.z); Bf[(r0+7)*128+lr]=dup2(pb1.w);
            __syncthreads();
        }
    }

    #pragma unroll
    for (int p=0;p<4;p++){
        int gm = m0 + ty*8 + p*2;
        #pragma unroll
        for (int jj=0;jj<4;jj++){
            int gn = n0 + 2*tx + 32*jj;
            if (gn < VV){
                float2 bb = *(const float2*)(bp + gn);
                union { ull u; float2 f; } c0, c1;
                c0.u = acc[p][2*jj]; c1.u = acc[p][2*jj+1];
                if (gm < NROW){
                    float2 r0 = make_float2(c0.f.x + bb.x, c1.f.x + bb.y);
                    *(float2*)(out + (size_t)gm*VV + gn) = r0;
                }
                if (gm+1 < NROW){
                    float2 r1 = make_float2(c0.f.y + bb.x, c1.f.y + bb.y);
                    *(float2*)(out + (size_t)(gm+1)*VV + gn) = r1;
                }
            }
        }
    }
}

// ---------------- row softmax stats ----------------
__global__ void __launch_bounds__(256) k_rowstats(const float* __restrict__ out)
{
    int row = blockIdx.x, tid = threadIdx.x;
    __shared__ float red[256];
    const float* r = out + (size_t)row*VV;
    float m = -1e30f;
    for (int i = tid; i < VV; i += 256) m = fmaxf(m, r[i]);
    red[tid] = m; __syncthreads();
    for (int st=128; st>0; st>>=1){ if (tid < st) red[tid] = fmaxf(red[tid], red[tid+st]); __syncthreads(); }
    m = red[0]; __syncthreads();
    float s = 0.f;
    for (int i = tid; i < VV; i += 256) s += __expf(r[i] - m);
    red[tid] = s; __syncthreads();
    for (int st=128; st>0; st>>=1){ if (tid < st) red[tid] += red[tid+st]; __syncthreads(); }
    if (tid == 0){
        g_rmax[row] = m;
        g_rscale[row] = g_pgen[row] / red[0];
    }
}

// ---------------- transform logits -> pgen*softmax + eps ----------------
__global__ void k_transform(float* __restrict__ out)
{
    int row = blockIdx.y;
    int p = blockIdx.x*256 + threadIdx.x;
    if (p >= VV/4) return;
    float m = g_rmax[row], sc = g_rscale[row];
    float4* o4 = (float4*)(out + (size_t)row*VV);
    float4 v = o4[p];
    v.x = sc*__expf(v.x - m) + EPSF;
    v.y = sc*__expf(v.y - m) + EPSF;
    v.z = sc*__expf(v.z - m) + EPSF;
    v.w = sc*__expf(v.w - m) + EPSF;
    o4[p] = v;
}

// ---------------- pointer scatter ----------------
__global__ void k_scatter(const int* __restrict__ x, float* __restrict__ out)
{
    int row = blockIdx.x, s = threadIdx.x;
    if (s >= SIN) return;
    int b = row / SOUT;
    float w = (1.f - g_pgen[row]) * g_attn[(size_t)row*SIN + s];
    atomicAdd(out + (size_t)row*VV + x[b*SIN + s], w);
}

// ---------------- final log ----------------
__global__ void k_log(float* __restrict__ out)
{
    int row = blockIdx.y;
    int p = blockIdx.x*256 + threadIdx.x;
    if (p >= VV/4) return;
    float4* o4 = (float4*)(out + (size_t)row*VV);
    float4 v = o4[p];
    v.x = logf(v.x); v.y = logf(v.y); v.z = logf(v.z); v.w = logf(v.w);
    o4[p] = v;
}

extern "C" void kernel_launch(void* const* d_in, const int* in_sizes, int n_in,
                              void* d_out, int out_size)
{
    const int*   x    = (const int*)  d_in[0];
    const int*   ans  = (const int*)  d_in[1];
    const float* emb  = (const float*)d_in[2];
    const float* wif  = (const float*)d_in[3];
    const float* ehf  = (const float*)d_in[4];
    const float* ebf  = (const float*)d_in[5];
    const float* wib  = (const float*)d_in[6];
    const float* ehb  = (const float*)d_in[7];
    const float* ebb  = (const float*)d_in[8];
    const float* wid_ = (const float*)d_in[9];
    const float* dwh  = (const float*)d_in[10];
    const float* db   = (const float*)d_in[11];
    const float* Wp   = (const float*)d_in[12];
    const float* bp   = (const float*)d_in[13];
    const float* wpg  = (const float*)d_in[14];
    const float* bpg  = (const float*)d_in[15];
    float* out = (float*)d_out;

    float* xgf; cudaGetSymbolAddress((void**)&xgf, g_xgf);
    float* xgb; cudaGetSymbolAddress((void**)&xgb, g_xgb);
    float* xgd; cudaGetSymbolAddress((void**)&xgd, g_xgd);

    k_transpose<<<dim3(1024,3), 256>>>(ehf, ehb, dwh);
    k_xg_gemm<<<dim3(8, 50), 256>>>(emb, wif, ebf, x, SIN, 0, BB*SIN, xgf);
    k_xg_gemm<<<dim3(8, 50), 256>>>(emb, wib, ebb, x, SIN, 1, BB*SIN, xgb);
    k_xg_gemm<<<dim3(16, 13), 256>>>(emb, wid_, db, ans, SOUT, 0, BB*SOUT, xgd);
    k_ansemb<<<NROW, 32>>>(ans, emb);
    k_enc<<<32, 256>>>();
    k_dec<<<BB, 256>>>();
    k_attn<<<NROW, 256>>>(wpg, bpg);
    k_gemm<<<dim3((VV+127)/128, (NROW+127)/128), 256>>>(Wp, bp, out);
    k_rowstats<<<NROW, 256>>>(out);
    k_transform<<<dim3((VV/4+255)/256, NROW), 256>>>(out);
    k_scatter<<<NROW, 512>>>(x, out);
    k_log<<<dim3((VV/4+255)/256, NROW), 256>>>(out);
}

// round 16
// speedup vs baseline: 1.5412x; 1.1476x over previous
#include <cuda_runtime.h>
#include <cuda_bf16.h>
#include <mma.h>
#include <math.h>
#include <stdint.h>

#define BB    16
#define SIN   400
#define SOUT  100
#define HH    256
#define EE    128
#define VV    50000
#define G4    1024
#define H2    512
#define G8    2048
#define NROW  (BB*SOUT)
#define EPSF  1e-10f

#define NPAD  50048            // 782 n-tiles of 64
#define MPAD  1664             // 13 m-tiles of 128
#define LDT   24               // padded smem row (bf16 elems)

using namespace nvcuda;

// ---------------- static device scratch ----------------
__device__ float4 g_WtEf4[256*256];
__device__ float4 g_WtEb4[256*256];
__device__ float4 g_WtD4 [512*512];
__device__ float  g_xgf[BB*SIN*G4];
__device__ float  g_xgb[BB*SIN*G4];
__device__ float  g_xgd[BB*SOUT*G8];
__device__ float  g_ansemb[BB*SOUT*EE];
__device__ float  g_xb[BB*SIN*H2];
__device__ float  g_h0[BB*H2];
__device__ float  g_c0[BB*H2];
__device__ float  g_feat[NROW*G4];
__device__ float  g_attn[NROW*SIN];
__device__ float  g_pgen[NROW];
__device__ float  g_rmax[NROW];
__device__ float  g_rscale[NROW];
__device__ __nv_bfloat16 g_Bhi[(size_t)NPAD*G4];
__device__ __nv_bfloat16 g_Blo[(size_t)NPAD*G4];
__device__ __nv_bfloat16 g_Ahi[(size_t)MPAD*G4];
__device__ __nv_bfloat16 g_Alo[(size_t)MPAD*G4];

__device__ __forceinline__ float sigm(float x){ return 1.f/(1.f+__expf(-x)); }
__device__ __forceinline__ float tanh_(float x){ return 2.f/(1.f+__expf(-2.f*x)) - 1.f; }

// ---------------- weight transposes (Whh only) ----------------
__global__ void k_transpose(const float* __restrict__ ef, const float* __restrict__ eb,
                            const float* __restrict__ dw)
{
    int job = blockIdx.y;
    int idx = blockIdx.x*256 + threadIdx.x;
    if (job == 0) {
        if (idx < 256*256){ int k = idx>>8, j = idx&255;
            g_WtEf4[idx] = make_float4(ef[j*256+k], ef[(256+j)*256+k], ef[(512+j)*256+k], ef[(768+j)*256+k]); }
    } else if (job == 1) {
        if (idx < 256*256){ int k = idx>>8, j = idx&255;
            g_WtEb4[idx] = make_float4(eb[j*256+k], eb[(256+j)*256+k], eb[(512+j)*256+k], eb[(768+j)*256+k]); }
    } else {
        if (idx < 512*512){ int k = idx>>9, c = idx&511;
            g_WtD4[idx] = make_float4(dw[c*512+k], dw[(512+c)*512+k], dw[(1024+c)*512+k], dw[(1536+c)*512+k]); }
    }
}

// ---------------- input-gate GEMM ----------------
__global__ void __launch_bounds__(256) k_xg_gemm(
    const float* __restrict__ emb, const float* __restrict__ W,
    const float* __restrict__ bias, const int* __restrict__ toks,
    int Tlen, int rev, int M, float* __restrict__ out)
{
    __shared__ float As[32][128];
    __shared__ float Bs[32][128];
    int n0 = blockIdx.x*128, m0 = blockIdx.y*128;
    int tid = threadIdx.x;
    int tx = tid & 15, ty = tid >> 4;
    int lr = tid >> 1;
    int lp = (tid & 1) * 4;
    size_t N = (size_t)gridDim.x * 128;

    int tokA = 0;
    int gmA = m0 + lr;
    if (gmA < M){
        int b = gmA / Tlen, t = gmA % Tlen;
        int tt = rev ? (Tlen-1-t) : t;
        tokA = toks[b*Tlen + tt];
    }
    int gnB = n0 + lr;

    float acc[8][8];
    #pragma unroll
    for (int i=0;i<8;i++)
        #pragma unroll
        for (int j=0;j<8;j++) acc[i][j] = 0.f;

    #pragma unroll
    for (int kc = 0; kc < 4; kc++){
        int f4base = kc*8;
        #pragma unroll
        for (int j=0;j<4;j++){
            int f4 = lp + j;
            float4 a = make_float4(0.f,0.f,0.f,0.f);
            if (gmA < M) a = ((const float4*)emb)[(size_t)tokA*32 + f4base + f4];
            int kk = f4*4;
            As[kk+0][lr]=a.x; As[kk+1][lr]=a.y; As[kk+2][lr]=a.z; As[kk+3][lr]=a.w;
            float4 bv = ((const float4*)W)[((size_t)gnB*128)/4 + f4base + f4];
            Bs[kk+0][lr]=bv.x; Bs[kk+1][lr]=bv.y; Bs[kk+2][lr]=bv.z; Bs[kk+3][lr]=bv.w;
        }
        __syncthreads();
        #pragma unroll
        for (int k=0;k<32;k++){
            float4 a0 = *(const float4*)&As[k][ty*8];
            float4 a1 = *(const float4*)&As[k][ty*8+4];
            float4 b0 = *(const float4*)&Bs[k][tx*8];
            float4 b1 = *(const float4*)&Bs[k][tx*8+4];
            float av[8] = {a0.x,a0.y,a0.z,a0.w,a1.x,a1.y,a1.z,a1.w};
            float bw[8] = {b0.x,b0.y,b0.z,b0.w,b1.x,b1.y,b1.z,b1.w};
            #pragma unroll
            for (int i=0;i<8;i++)
                #pragma unroll
                for (int j=0;j<8;j++) acc[i][j] = fmaf(av[i], bw[j], acc[i][j]);
        }
        __syncthreads();
    }

    #pragma unroll
    for (int i=0;i<8;i++){
        int gm = m0 + ty*8 + i;
        if (gm < M){
            #pragma unroll
            for (int j=0;j<8;j++){
                int gn = n0 + tx*8 + j;
                out[(size_t)gm*N + gn] = acc[i][j] + bias[gn];
            }
        }
    }
}

// ---------------- ans embedding copy ----------------
__global__ void k_ansemb(const int* __restrict__ ans, const float* __restrict__ emb)
{
    int row = blockIdx.x, v = threadIdx.x;
    int tok = ans[row];
    ((float4*)g_ansemb)[(size_t)row*32 + v] = ((const float4*)emb)[(size_t)tok*32 + v];
}

// ---------------- encoder BiLSTM ----------------
__global__ void __launch_bounds__(256) k_enc()
{
    int dir = blockIdx.x >> 4, b = blockIdx.x & 15;
    const float4* __restrict__ Wt = dir ? g_WtEb4 : g_WtEf4;
    const float* xg = (dir ? g_xgb : g_xgf) + (size_t)b*SIN*G4;
    __shared__ float hs[256];
    int j = threadIdx.x;
    float c = 0.f, hn = 0.f;
    hs[j] = 0.f;
    __syncthreads();
    for (int t=0;t<SIN;t++){
        const float* xr = xg + (size_t)t*G4;
        float gi=xr[j], gf=xr[256+j], gg=xr[512+j], go=xr[768+j];
        #pragma unroll 8
        for (int k=0;k<256;k++){
            float hk = hs[k];
            float4 w = Wt[k*256 + j];
            gi = fmaf(w.x, hk, gi); gf = fmaf(w.y, hk, gf);
            gg = fmaf(w.z, hk, gg); go = fmaf(w.w, hk, go);
        }
        float cn = sigm(gf)*c + sigm(gi)*tanh_(gg);
        hn = sigm(go)*tanh_(cn);
        c = cn;
        __syncthreads();
        hs[j] = hn;
        int tp = dir ? (SIN-1-t) : t;
        g_xb[(size_t)(b*SIN + tp)*H2 + dir*256 + j] = hn;
        __syncthreads();
    }
    g_h0[b*H2 + dir*256 + j] = hn;
    g_c0[b*H2 + dir*256 + j] = c;
}

// ---------------- decoder LSTM ----------------
__global__ void __launch_bounds__(256) k_dec()
{
    int b = blockIdx.x, j = threadIdx.x;
    __shared__ float hs[512];
    float c0 = g_c0[b*H2 + j], c1 = g_c0[b*H2 + 256 + j];
    hs[j]     = g_h0[b*H2 + j];
    hs[256+j] = g_h0[b*H2 + 256 + j];
    __syncthreads();
    for (int t=0;t<SOUT;t++){
        const float* xr = g_xgd + (size_t)(b*SOUT + t)*G8;
        float ai=xr[j],     af=xr[512+j],  ag=xr[1024+j], ao=xr[1536+j];
        float bi=xr[256+j], bf=xr[768+j],  bg=xr[1280+j], bo=xr[1792+j];
        #pragma unroll 4
        for (int k=0;k<512;k++){
            float hk = hs[k];
            float4 w0 = g_WtD4[k*512 + j];
            float4 w1 = g_WtD4[k*512 + 256 + j];
            ai=fmaf(w0.x,hk,ai); af=fmaf(w0.y,hk,af); ag=fmaf(w0.z,hk,ag); ao=fmaf(w0.w,hk,ao);
            bi=fmaf(w1.x,hk,bi); bf=fmaf(w1.y,hk,bf); bg=fmaf(w1.z,hk,bg); bo=fmaf(w1.w,hk,bo);
        }
        float cn0 = sigm(af)*c0 + sigm(ai)*tanh_(ag);
        float h0n = sigm(ao)*tanh_(cn0);
        float cn1 = sigm(bf)*c1 + sigm(bi)*tanh_(bg);
        float h1n = sigm(bo)*tanh_(cn1);
        c0 = cn0; c1 = cn1;
        __syncthreads();
        hs[j] = h0n; hs[256+j] = h1n;
        float* fr = g_feat + (size_t)(b*SOUT + t)*G4;
        fr[j] = h0n; fr[256+j] = h1n;
        __syncthreads();
    }
}

// ---------------- attention + context + pgen ----------------
__global__ void __launch_bounds__(256) k_attn(const float* __restrict__ wpg, const float* __restrict__ bpg)
{
    int row = blockIdx.x;
    int b = row / SOUT;
    __shared__ float ds[512];
    __shared__ float ctx[512];
    __shared__ float sc[SIN];
    __shared__ float red[256];
    int tid = threadIdx.x, lane = tid & 31, wid = tid >> 5;
    float* feat = g_feat + (size_t)row*G4;
    ds[tid] = feat[tid]; ds[256+tid] = feat[256+tid];
    __syncthreads();

    const float4* ds4 = (const float4*)ds;
    for (int s = wid; s < SIN; s += 8){
        const float4* xr = (const float4*)(g_xb + (size_t)(b*SIN + s)*H2);
        float acc = 0.f;
        #pragma unroll
        for (int i=0;i<4;i++){
            float4 a = xr[lane + i*32];
            float4 d = ds4[lane + i*32];
            acc += a.x*d.x + a.y*d.y + a.z*d.z + a.w*d.w;
        }
        #pragma unroll
        for (int o=16;o>0;o>>=1) acc += __shfl_xor_sync(0xffffffffu, acc, o);
        if (lane == 0) sc[s] = acc;
    }
    __syncthreads();

    float m = -1e30f;
    for (int s = tid; s < SIN; s += 256) m = fmaxf(m, sc[s]);
    red[tid] = m; __syncthreads();
    for (int st=128; st>0; st>>=1){ if (tid < st) red[tid] = fmaxf(red[tid], red[tid+st]); __syncthreads(); }
    m = red[0]; __syncthreads();
    float ssum = 0.f;
    for (int s = tid; s < SIN; s += 256) ssum += __expf(sc[s] - m);
    red[tid] = ssum; __syncthreads();
    for (int st=128; st>0; st>>=1){ if (tid < st) red[tid] += red[tid+st]; __syncthreads(); }
    float inv = 1.f / red[0]; __syncthreads();
    for (int s = tid; s < SIN; s += 256){
        float a = __expf(sc[s] - m) * inv;
        sc[s] = a;
        g_attn[(size_t)row*SIN + s] = a;
    }
    __syncthreads();

    #pragma unroll
    for (int h=0; h<2; h++){
        int d = tid + h*256;
        float acc = 0.f;
        const float* xp = g_xb + (size_t)b*SIN*H2 + d;
        for (int s=0; s<SIN; s++) acc = fmaf(sc[s], xp[(size_t)s*H2], acc);
        ctx[d] = acc;
        feat[512 + d] = acc;
    }
    __syncthreads();

    float p = 0.f;
    #pragma unroll
    for (int h=0; h<2; h++){
        int i = tid + h*256;
        p += wpg[i]*ctx[i] + wpg[512+i]*ds[i];
    }
    if (tid < 128) p += wpg[1024+tid] * g_ansemb[(size_t)row*EE + tid];
    red[tid] = p; __syncthreads();
    for (int st=128; st>0; st>>=1){ if (tid < st) red[tid] += red[tid+st]; __syncthreads(); }
    if (tid == 0) g_pgen[row] = sigm(red[0] + bpg[0]);
}

// ---------------- split fp32 -> bf16 hi/lo ----------------
__global__ void k_cvtB(const float* __restrict__ Wp)
{
    size_t i = ((size_t)blockIdx.x*256 + threadIdx.x)*8;
    if (i >= (size_t)NPAD*G4) return;
    __nv_bfloat16 hi8[8], lo8[8];
    if (i < (size_t)VV*G4){
        float4 a = *(const float4*)(Wp + i);
        float4 b = *(const float4*)(Wp + i + 4);
        float v[8] = {a.x,a.y,a.z,a.w,b.x,b.y,b.z,b.w};
        #pragma unroll
        for (int j=0;j<8;j++){
            __nv_bfloat16 hv = __float2bfloat16_rn(v[j]);
            hi8[j] = hv;
            lo8[j] = __float2bfloat16_rn(v[j] - __bfloat162float(hv));
        }
    } else {
        #pragma unroll
        for (int j=0;j<8;j++){ hi8[j] = __float2bfloat16_rn(0.f); lo8[j] = hi8[j]; }
    }
    ((uint4*)g_Bhi)[i/8] = *(const uint4*)hi8;
    ((uint4*)g_Blo)[i/8] = *(const uint4*)lo8;
}

__global__ void k_cvtA()
{
    size_t i = ((size_t)blockIdx.x*256 + threadIdx.x)*8;
    if (i >= (size_t)MPAD*G4) return;
    __nv_bfloat16 hi8[8], lo8[8];
    if (i < (size_t)NROW*G4){
        float4 a = *(const float4*)(g_feat + i);
        float4 b = *(const float4*)(g_feat + i + 4);
        float v[8] = {a.x,a.y,a.z,a.w,b.x,b.y,b.z,b.w};
        #pragma unroll
        for (int j=0;j<8;j++){
            __nv_bfloat16 hv = __float2bfloat16_rn(v[j]);
            hi8[j] = hv;
            lo8[j] = __float2bfloat16_rn(v[j] - __bfloat162float(hv));
        }
    } else {
        #pragma unroll
        for (int j=0;j<8;j++){ hi8[j] = __float2bfloat16_rn(0.f); lo8[j] = hi8[j]; }
    }
    ((uint4*)g_Ahi)[i/8] = *(const uint4*)hi8;
    ((uint4*)g_Alo)[i/8] = *(const uint4*)lo8;
}

// ---------------- projection GEMM via wmma bf16 hi/lo split ----------------
// out[m][n] = sum_k feat[m][k] * Wp[n][k]   (bias folded into rowstats/transform)
__global__ void __launch_bounds__(256) k_wmma(float* __restrict__ out)
{
    __shared__ __align__(16) __nv_bfloat16 Ah[2][128*LDT];
    __shared__ __align__(16) __nv_bfloat16 Al[2][128*LDT];
    __shared__ __align__(16) __nv_bfloat16 Bh[2][64*LDT];
    __shared__ __align__(16) __nv_bfloat16 Bl[2][64*LDT];

    int tid = threadIdx.x, w = tid >> 5;
    int n0 = blockIdx.x*64, m0 = blockIdx.y*128;
    int wm = (w & 3) * 32, wn = (w >> 2) * 32;

    wmma::fragment<wmma::accumulator,16,16,16,float> cf[2][2];
    #pragma unroll
    for (int i=0;i<2;i++)
        #pragma unroll
        for (int j=0;j<2;j++) wmma::fill_fragment(cf[i][j], 0.f);

    int ar = tid >> 1, ak = (tid & 1) * 8;
    int br = (tid & 127) >> 1, bk = (tid & 1) * 8;
    bool isBh = tid < 128;
    const __nv_bfloat16* Bsrc = isBh ? g_Bhi : g_Blo;

    uint4 pah, pal, pbx;
    pah = *(const uint4*)(g_Ahi + (size_t)(m0+ar)*G4 + ak);
    pal = *(const uint4*)(g_Alo + (size_t)(m0+ar)*G4 + ak);
    pbx = *(const uint4*)(Bsrc + (size_t)(n0+br)*G4 + bk);
    *(uint4*)(&Ah[0][ar*LDT + ak]) = pah;
    *(uint4*)(&Al[0][ar*LDT + ak]) = pal;
    if (isBh) *(uint4*)(&Bh[0][br*LDT + bk]) = pbx;
    else      *(uint4*)(&Bl[0][br*LDT + bk]) = pbx;
    __syncthreads();

    for (int kc = 0; kc < 64; kc++){
        int cur = kc & 1, nxt = cur ^ 1;
        if (kc + 1 < 64){
            int ko = (kc+1)*16;
            pah = *(const uint4*)(g_Ahi + (size_t)(m0+ar)*G4 + ko + ak);
            pal = *(const uint4*)(g_Alo + (size_t)(m0+ar)*G4 + ko + ak);
            pbx = *(const uint4*)(Bsrc + (size_t)(n0+br)*G4 + ko + bk);
        }
        wmma::fragment<wmma::matrix_a,16,16,16,__nv_bfloat16,wmma::row_major> fah[2], fal[2];
        wmma::fragment<wmma::matrix_b,16,16,16,__nv_bfloat16,wmma::col_major> fbh[2], fbl[2];
        #pragma unroll
        for (int i=0;i<2;i++){
            wmma::load_matrix_sync(fah[i], &Ah[cur][(wm + i*16)*LDT], LDT);
            wmma::load_matrix_sync(fal[i], &Al[cur][(wm + i*16)*LDT], LDT);
            wmma::load_matrix_sync(fbh[i], &Bh[cur][(wn + i*16)*LDT], LDT);
            wmma::load_matrix_sync(fbl[i], &Bl[cur][(wn + i*16)*LDT], LDT);
        }
        #pragma unroll
        for (int i=0;i<2;i++)
            #pragma unroll
            for (int j=0;j<2;j++){
                wmma::mma_sync(cf[i][j], fah[i], fbh[j], cf[i][j]);
                wmma::mma_sync(cf[i][j], fah[i], fbl[j], cf[i][j]);
                wmma::mma_sync(cf[i][j], fal[i], fbh[j], cf[i][j]);
            }
        if (kc + 1 < 64){
            *(uint4*)(&Ah[nxt][ar*LDT + ak]) = pah;
            *(uint4*)(&Al[nxt][ar*LDT + ak]) = pal;
            if (isBh) *(uint4*)(&Bh[nxt][br*LDT + bk]) = pbx;
            else      *(uint4*)(&Bl[nxt][br*LDT + bk]) = pbx;
        }
        __syncthreads();
    }

    #pragma unroll
    for (int i=0;i<2;i++){
        int gm = m0 + wm + i*16;
        if (gm + 16 <= NROW){
            #pragma unroll
            for (int j=0;j<2;j++){
                int gn = n0 + wn + j*16;
                if (gn + 16 <= VV)
                    wmma::store_matrix_sync(out + (size_t)gm*VV + gn, cf[i][j], VV, wmma::mem_row_major);
            }
        }
    }
}

// ---------------- row softmax stats (bias folded in) ----------------
__global__ void __launch_bounds__(256) k_rowstats(const float* __restrict__ out, const float* __restrict__ bp)
{
    int row = blockIdx.x, tid = threadIdx.x;
    __shared__ float red[256];
    const float* r = out + (size_t)row*VV;
    float m = -1e30f;
    for (int i = tid; i < VV; i += 256) m = fmaxf(m, r[i] + bp[i]);
    red[tid] = m; __syncthreads();
    for (int st=128; st>0; st>>=1){ if (tid < st) red[tid] = fmaxf(red[tid], red[tid+st]); __syncthreads(); }
    m = red[0]; __syncthreads();
    float s = 0.f;
    for (int i = tid; i < VV; i += 256) s += __expf(r[i] + bp[i] - m);
    red[tid] = s; __syncthreads();
    for (int st=128; st>0; st>>=1){ if (tid < st) red[tid] += red[tid+st]; __syncthreads(); }
    if (tid == 0){
        g_rmax[row] = m;
        g_rscale[row] = g_pgen[row] / red[0];
    }
}

// ---------------- transform logits -> pgen*softmax + eps (bias folded in) ----------------
__global__ void k_transform(float* __restrict__ out, const float* __restrict__ bp)
{
    int row = blockIdx.y;
    int p = blockIdx.x*256 + threadIdx.x;
    if (p >= VV/4) return;
    float m = g_rmax[row], sc = g_rscale[row];
    float4* o4 = (float4*)(out + (size_t)row*VV);
    float4 v = o4[p];
    float4 bb = ((const float4*)bp)[p];
    v.x = sc*__expf(v.x + bb.x - m) + EPSF;
    v.y = sc*__expf(v.y + bb.y - m) + EPSF;
    v.z = sc*__expf(v.z + bb.z - m) + EPSF;
    v.w = sc*__expf(v.w + bb.w - m) + EPSF;
    o4[p] = v;
}

// ---------------- pointer scatter ----------------
__global__ void k_scatter(const int* __restrict__ x, float* __restrict__ out)
{
    int row = blockIdx.x, s = threadIdx.x;
    if (s >= SIN) return;
    int b = row / SOUT;
    float w = (1.f - g_pgen[row]) * g_attn[(size_t)row*SIN + s];
    atomicAdd(out + (size_t)row*VV + x[b*SIN + s], w);
}

// ---------------- final log ----------------
__global__ void k_log(float* __restrict__ out)
{
    int row = blockIdx.y;
    int p = blockIdx.x*256 + threadIdx.x;
    if (p >= VV/4) return;
    float4* o4 = (float4*)(out + (size_t)row*VV);
    float4 v = o4[p];
    v.x = logf(v.x); v.y = logf(v.y); v.z = logf(v.z); v.w = logf(v.w);
    o4[p] = v;
}

extern "C" void kernel_launch(void* const* d_in, const int* in_sizes, int n_in,
                              void* d_out, int out_size)
{
    const int*   x    = (const int*)  d_in[0];
    const int*   ans  = (const int*)  d_in[1];
    const float* emb  = (const float*)d_in[2];
    const float* wif  = (const float*)d_in[3];
    const float* ehf  = (const float*)d_in[4];
    const float* ebf  = (const float*)d_in[5];
    const float* wib  = (const float*)d_in[6];
    const float* ehb  = (const float*)d_in[7];
    const float* ebb  = (const float*)d_in[8];
    const float* wid_ = (const float*)d_in[9];
    const float* dwh  = (const float*)d_in[10];
    const float* db   = (const float*)d_in[11];
    const float* Wp   = (const float*)d_in[12];
    const float* bp   = (const float*)d_in[13];
    const float* wpg  = (const float*)d_in[14];
    const float* bpg  = (const float*)d_in[15];
    float* out = (float*)d_out;

    float* xgf; cudaGetSymbolAddress((void**)&xgf, g_xgf);
    float* xgb; cudaGetSymbolAddress((void**)&xgb, g_xgb);
    float* xgd; cudaGetSymbolAddress((void**)&xgd, g_xgd);

    k_cvtB<<<(int)(((size_t)NPAD*G4/8 + 255)/256), 256>>>(Wp);
    k_transpose<<<dim3(1024,3), 256>>>(ehf, ehb, dwh);
    k_xg_gemm<<<dim3(8, 50), 256>>>(emb, wif, ebf, x, SIN, 0, BB*SIN, xgf);
    k_xg_gemm<<<dim3(8, 50), 256>>>(emb, wib, ebb, x, SIN, 1, BB*SIN, xgb);
    k_xg_gemm<<<dim3(16, 13), 256>>>(emb, wid_, db, ans, SOUT, 0, BB*SOUT, xgd);
    k_ansemb<<<NROW, 32>>>(ans, emb);
    k_enc<<<32, 256>>>();
    k_dec<<<BB, 256>>>();
    k_attn<<<NROW, 256>>>(wpg, bpg);
    k_cvtA<<<(int)(((size_t)MPAD*G4/8 + 255)/256), 256>>>();
    k_wmma<<<dim3(NPAD/64, MPAD/128), 256>>>(out);
    k_rowstats<<<NROW, 256>>>(out, bp);
    k_transform<<<dim3((VV/4+255)/256, NROW), 256>>>(out, bp);
    k_scatter<<<NROW, 512>>>(x, out);
    k_log<<<dim3((VV/4+255)/256, NROW), 256>>>(out);
}

// round 17
// speedup vs baseline: 4.4489x; 2.8866x over previous
#include <cuda_runtime.h>
#include <cuda_bf16.h>
#include <mma.h>
#include <math.h>
#include <stdint.h>

#define BB    16
#define SIN   400
#define SOUT  100
#define HH    256
#define EE    128
#define VV    50000
#define G4    1024
#define H2    512
#define G8    2048
#define NROW  (BB*SOUT)
#define EPSF  1e-10f

#define NPAD  50048
#define MPAD  1664
#define LDT   24

using namespace nvcuda;

// ---------------- static device scratch ----------------
__device__ float4 g_WtEf4[256*256];
__device__ float4 g_WtEb4[256*256];
__device__ float4 g_WtD4 [512*512];
__device__ float  g_xgf[BB*SIN*G4];
__device__ float  g_xgb[BB*SIN*G4];
__device__ float  g_xgd[BB*SOUT*G8];
__device__ float  g_ansemb[BB*SOUT*EE];
__device__ float  g_xb[BB*SIN*H2];
__device__ float  g_h0[BB*H2];
__device__ float  g_c0[BB*H2];
__device__ float  g_feat[NROW*G4];
__device__ float  g_attn[NROW*SIN];
__device__ float  g_pgen[NROW];
__device__ float  g_rmax[NROW];
__device__ float  g_rscale[NROW];
__device__ float  g_hworkE[32*256];
__device__ float  g_hworkD[16*512];
__device__ __nv_bfloat16 g_Bhi[(size_t)NPAD*G4];
__device__ __nv_bfloat16 g_Blo[(size_t)NPAD*G4];
__device__ __nv_bfloat16 g_Ahi[(size_t)MPAD*G4];
__device__ __nv_bfloat16 g_Alo[(size_t)MPAD*G4];

__device__ __forceinline__ float sigm(float x){ return 1.f/(1.f+__expf(-x)); }
__device__ __forceinline__ float tanh_(float x){ return 2.f/(1.f+__expf(-2.f*x)) - 1.f; }

// ---------------- weight transposes (Whh only) ----------------
__global__ void k_transpose(const float* __restrict__ ef, const float* __restrict__ eb,
                            const float* __restrict__ dw)
{
    int job = blockIdx.y;
    int idx = blockIdx.x*256 + threadIdx.x;
    if (job == 0) {
        if (idx < 256*256){ int k = idx>>8, j = idx&255;
            g_WtEf4[idx] = make_float4(ef[j*256+k], ef[(256+j)*256+k], ef[(512+j)*256+k], ef[(768+j)*256+k]); }
    } else if (job == 1) {
        if (idx < 256*256){ int k = idx>>8, j = idx&255;
            g_WtEb4[idx] = make_float4(eb[j*256+k], eb[(256+j)*256+k], eb[(512+j)*256+k], eb[(768+j)*256+k]); }
    } else {
        if (idx < 512*512){ int k = idx>>9, c = idx&511;
            g_WtD4[idx] = make_float4(dw[c*512+k], dw[(512+c)*512+k], dw[(1024+c)*512+k], dw[(1536+c)*512+k]); }
    }
}

// ---------------- input-gate GEMM ----------------
__global__ void __launch_bounds__(256) k_xg_gemm(
    const float* __restrict__ emb, const float* __restrict__ W,
    const float* __restrict__ bias, const int* __restrict__ toks,
    int Tlen, int rev, int M, float* __restrict__ out)
{
    __shared__ float As[32][128];
    __shared__ float Bs[32][128];
    int n0 = blockIdx.x*128, m0 = blockIdx.y*128;
    int tid = threadIdx.x;
    int tx = tid & 15, ty = tid >> 4;
    int lr = tid >> 1;
    int lp = (tid & 1) * 4;
    size_t N = (size_t)gridDim.x * 128;

    int tokA = 0;
    int gmA = m0 + lr;
    if (gmA < M){
        int b = gmA / Tlen, t = gmA % Tlen;
        int tt = rev ? (Tlen-1-t) : t;
        tokA = toks[b*Tlen + tt];
    }
    int gnB = n0 + lr;

    float acc[8][8];
    #pragma unroll
    for (int i=0;i<8;i++)
        #pragma unroll
        for (int j=0;j<8;j++) acc[i][j] = 0.f;

    #pragma unroll
    for (int kc = 0; kc < 4; kc++){
        int f4base = kc*8;
        #pragma unroll
        for (int j=0;j<4;j++){
            int f4 = lp + j;
            float4 a = make_float4(0.f,0.f,0.f,0.f);
            if (gmA < M) a = ((const float4*)emb)[(size_t)tokA*32 + f4base + f4];
            int kk = f4*4;
            As[kk+0][lr]=a.x; As[kk+1][lr]=a.y; As[kk+2][lr]=a.z; As[kk+3][lr]=a.w;
            float4 bv = ((const float4*)W)[((size_t)gnB*128)/4 + f4base + f4];
            Bs[kk+0][lr]=bv.x; Bs[kk+1][lr]=bv.y; Bs[kk+2][lr]=bv.z; Bs[kk+3][lr]=bv.w;
        }
        __syncthreads();
        #pragma unroll
        for (int k=0;k<32;k++){
            float4 a0 = *(const float4*)&As[k][ty*8];
            float4 a1 = *(const float4*)&As[k][ty*8+4];
            float4 b0 = *(const float4*)&Bs[k][tx*8];
            float4 b1 = *(const float4*)&Bs[k][tx*8+4];
            float av[8] = {a0.x,a0.y,a0.z,a0.w,a1.x,a1.y,a1.z,a1.w};
            float bw[8] = {b0.x,b0.y,b0.z,b0.w,b1.x,b1.y,b1.z,b1.w};
            #pragma unroll
            for (int i=0;i<8;i++)
                #pragma unroll
                for (int j=0;j<8;j++) acc[i][j] = fmaf(av[i], bw[j], acc[i][j]);
        }
        __syncthreads();
    }

    #pragma unroll
    for (int i=0;i<8;i++){
        int gm = m0 + ty*8 + i;
        if (gm < M){
            #pragma unroll
            for (int j=0;j<8;j++){
                int gn = n0 + tx*8 + j;
                out[(size_t)gm*N + gn] = acc[i][j] + bias[gn];
            }
        }
    }
}

// ---------------- ans embedding copy ----------------
__global__ void k_ansemb(const int* __restrict__ ans, const float* __restrict__ emb)
{
    int row = blockIdx.x, v = threadIdx.x;
    int tok = ans[row];
    ((float4*)g_ansemb)[(size_t)row*32 + v] = ((const float4*)emb)[(size_t)tok*32 + v];
}

// ---------------- encoder BiLSTM: cluster of 4 blocks per (dir, b-pair) ----------------
// grid = 64: blockIdx.x = cid*4 + r; cid: dir = cid>>3, bpair = cid&7.
// Block r owns cells [r*64, r*64+64) for BOTH samples of the pair.
__global__ __launch_bounds__(256, 1) __cluster_dims__(4, 1, 1) void k_enc2()
{
    int r   = blockIdx.x & 3;
    int cid = blockIdx.x >> 2;
    int dir = cid >> 3;
    int bp  = cid & 7;
    int b0 = bp*2, b1 = bp*2 + 1;
    const float4* __restrict__ Wt = dir ? g_WtEb4 : g_WtEf4;
    const float* xgbase = dir ? g_xgb : g_xgf;

    __shared__ float  h_sh[2][256];
    __shared__ float4 red[4][2][64];

    int t  = threadIdx.x;
    int cl = t & 63, kq = t >> 6;
    int j  = r*64 + cl;

    h_sh[0][t] = 0.f;
    h_sh[1][t] = 0.f;

    // owner state (threads t<128): bsel = t>>6, cell = cl
    int bsel = t >> 6;
    int bb   = bp*2 + bsel;
    float cstate = 0.f, hstate = 0.f;
    __syncthreads();

    for (int st = 0; st < SIN; st++){
        // partial gate sums over k in [kq*64, kq*64+64)
        float4 a0 = make_float4(0.f,0.f,0.f,0.f);
        float4 a1 = make_float4(0.f,0.f,0.f,0.f);
        const float4* wp  = Wt + (size_t)(kq*64)*256 + j;
        const float*  hp0 = &h_sh[0][kq*64];
        const float*  hp1 = &h_sh[1][kq*64];
        #pragma unroll 8
        for (int k=0;k<64;k++){
            float4 w = wp[(size_t)k*256];
            float ha = hp0[k], hb = hp1[k];
            a0.x = fmaf(w.x,ha,a0.x); a0.y = fmaf(w.y,ha,a0.y);
            a0.z = fmaf(w.z,ha,a0.z); a0.w = fmaf(w.w,ha,a0.w);
            a1.x = fmaf(w.x,hb,a1.x); a1.y = fmaf(w.y,hb,a1.y);
            a1.z = fmaf(w.z,hb,a1.z); a1.w = fmaf(w.w,hb,a1.w);
        }
        red[kq][0][cl] = a0;
        red[kq][1][cl] = a1;
        __syncthreads();
        if (t < 128){
            float4 s0 = red[0][bsel][cl];
            float4 s1 = red[1][bsel][cl];
            float4 s2 = red[2][bsel][cl];
            float4 s3 = red[3][bsel][cl];
            const float* xr = xgbase + ((size_t)bb*SIN + st)*G4;
            float gi = s0.x+s1.x+s2.x+s3.x + xr[j];
            float gf = s0.y+s1.y+s2.y+s3.y + xr[256+j];
            float gg = s0.z+s1.z+s2.z+s3.z + xr[512+j];
            float go = s0.w+s1.w+s2.w+s3.w + xr[768+j];
            float cn = sigm(gf)*cstate + sigm(gi)*tanh_(gg);
            hstate = sigm(go)*tanh_(cn);
            cstate = cn;
            int tp = dir ? (SIN-1-st) : st;
            g_xb[(size_t)(bb*SIN + tp)*H2 + dir*256 + j] = hstate;
            g_hworkE[(dir*16 + bb)*256 + j] = hstate;
            __threadfence();
        }
        __syncthreads();
        asm volatile("barrier.cluster.arrive.aligned;" ::: "memory");
        asm volatile("barrier.cluster.wait.aligned;" ::: "memory");
        h_sh[0][t] = __ldcg(&g_hworkE[(dir*16 + b0)*256 + t]);
        h_sh[1][t] = __ldcg(&g_hworkE[(dir*16 + b1)*256 + t]);
        __syncthreads();
    }
    if (t < 128){
        g_h0[bb*H2 + dir*256 + j] = hstate;
        g_c0[bb*H2 + dir*256 + j] = cstate;
    }
}

// ---------------- decoder LSTM: cluster of 8 blocks per b-pair ----------------
// grid = 64: blockIdx.x = bp*8 + r. Block r owns cells [r*64, r*64+64) of 512.
__global__ __launch_bounds__(256, 1) __cluster_dims__(8, 1, 1) void k_dec2()
{
    int r  = blockIdx.x & 7;
    int bp = blockIdx.x >> 3;
    int b0 = bp*2, b1 = bp*2 + 1;

    __shared__ float  h_sh[2][512];
    __shared__ float4 red[4][2][64];

    int t  = threadIdx.x;
    int cl = t & 63, kq = t >> 6;
    int j  = r*64 + cl;

    // init h from g_h0 (plain loads: fresh launch, L1 flushed)
    h_sh[0][t]       = g_h0[b0*H2 + t];
    h_sh[0][t + 256] = g_h0[b0*H2 + t + 256];
    h_sh[1][t]       = g_h0[b1*H2 + t];
    h_sh[1][t + 256] = g_h0[b1*H2 + t + 256];

    int bsel = t >> 6;
    int bb   = bp*2 + bsel;
    float cstate = (t < 128) ? g_c0[bb*H2 + j] : 0.f;
    __syncthreads();

    for (int st = 0; st < SOUT; st++){
        float4 a0 = make_float4(0.f,0.f,0.f,0.f);
        float4 a1 = make_float4(0.f,0.f,0.f,0.f);
        const float4* wp  = g_WtD4 + (size_t)(kq*128)*512 + j;
        const float*  hp0 = &h_sh[0][kq*128];
        const float*  hp1 = &h_sh[1][kq*128];
        #pragma unroll 8
        for (int k=0;k<128;k++){
            float4 w = wp[(size_t)k*512];
            float ha = hp0[k], hb = hp1[k];
            a0.x = fmaf(w.x,ha,a0.x); a0.y = fmaf(w.y,ha,a0.y);
            a0.z = fmaf(w.z,ha,a0.z); a0.w = fmaf(w.w,ha,a0.w);
            a1.x = fmaf(w.x,hb,a1.x); a1.y = fmaf(w.y,hb,a1.y);
            a1.z = fmaf(w.z,hb,a1.z); a1.w = fmaf(w.w,hb,a1.w);
        }
        red[kq][0][cl] = a0;
        red[kq][1][cl] = a1;
        __syncthreads();
        if (t < 128){
            float4 s0 = red[0][bsel][cl];
            float4 s1 = red[1][bsel][cl];
            float4 s2 = red[2][bsel][cl];
            float4 s3 = red[3][bsel][cl];
            const float* xr = g_xgd + ((size_t)bb*SOUT + st)*G8;
            float gi = s0.x+s1.x+s2.x+s3.x + xr[j];
            float gf = s0.y+s1.y+s2.y+s3.y + xr[512+j];
            float gg = s0.z+s1.z+s2.z+s3.z + xr[1024+j];
            float go = s0.w+s1.w+s2.w+s3.w + xr[1536+j];
            float cn = sigm(gf)*cstate + sigm(gi)*tanh_(gg);
            float hn = sigm(go)*tanh_(cn);
            cstate = cn;
            g_feat[(size_t)(bb*SOUT + st)*G4 + j] = hn;
            g_hworkD[bb*512 + j] = hn;
            __threadfence();
        }
        __syncthreads();
        asm volatile("barrier.cluster.arrive.aligned;" ::: "memory");
        asm volatile("barrier.cluster.wait.aligned;" ::: "memory");
        h_sh[0][t]       = __ldcg(&g_hworkD[b0*512 + t]);
        h_sh[0][t + 256] = __ldcg(&g_hworkD[b0*512 + t + 256]);
        h_sh[1][t]       = __ldcg(&g_hworkD[b1*512 + t]);
        h_sh[1][t + 256] = __ldcg(&g_hworkD[b1*512 + t + 256]);
        __syncthreads();
    }
}

// ---------------- attention + context + pgen ----------------
__global__ void __launch_bounds__(256) k_attn(const float* __restrict__ wpg, const float* __restrict__ bpg)
{
    int row = blockIdx.x;
    int b = row / SOUT;
    __shared__ float ds[512];
    __shared__ float ctx[512];
    __shared__ float sc[SIN];
    __shared__ float red[256];
    int tid = threadIdx.x, lane = tid & 31, wid = tid >> 5;
    float* feat = g_feat + (size_t)row*G4;
    ds[tid] = feat[tid]; ds[256+tid] = feat[256+tid];
    __syncthreads();

    const float4* ds4 = (const float4*)ds;
    for (int s = wid; s < SIN; s += 8){
        const float4* xr = (const float4*)(g_xb + (size_t)(b*SIN + s)*H2);
        float acc = 0.f;
        #pragma unroll
        for (int i=0;i<4;i++){
            float4 a = xr[lane + i*32];
            float4 d = ds4[lane + i*32];
            acc += a.x*d.x + a.y*d.y + a.z*d.z + a.w*d.w;
        }
        #pragma unroll
        for (int o=16;o>0;o>>=1) acc += __shfl_xor_sync(0xffffffffu, acc, o);
        if (lane == 0) sc[s] = acc;
    }
    __syncthreads();

    float m = -1e30f;
    for (int s = tid; s < SIN; s += 256) m = fmaxf(m, sc[s]);
    red[tid] = m; __syncthreads();
    for (int st=128; st>0; st>>=1){ if (tid < st) red[tid] = fmaxf(red[tid], red[tid+st]); __syncthreads(); }
    m = red[0]; __syncthreads();
    float ssum = 0.f;
    for (int s = tid; s < SIN; s += 256) ssum += __expf(sc[s] - m);
    red[tid] = ssum; __syncthreads();
    for (int st=128; st>0; st>>=1){ if (tid < st) red[tid] += red[tid+st]; __syncthreads(); }
    float inv = 1.f / red[0]; __syncthreads();
    for (int s = tid; s < SIN; s += 256){
        float a = __expf(sc[s] - m) * inv;
        sc[s] = a;
        g_attn[(size_t)row*SIN + s] = a;
    }
    __syncthreads();

    #pragma unroll
    for (int h=0; h<2; h++){
        int d = tid + h*256;
        float acc = 0.f;
        const float* xp = g_xb + (size_t)b*SIN*H2 + d;
        for (int s=0; s<SIN; s++) acc = fmaf(sc[s], xp[(size_t)s*H2], acc);
        ctx[d] = acc;
        feat[512 + d] = acc;
    }
    __syncthreads();

    float p = 0.f;
    #pragma unroll
    for (int h=0; h<2; h++){
        int i = tid + h*256;
        p += wpg[i]*ctx[i] + wpg[512+i]*ds[i];
    }
    if (tid < 128) p += wpg[1024+tid] * g_ansemb[(size_t)row*EE + tid];
    red[tid] = p; __syncthreads();
    for (int st=128; st>0; st>>=1){ if (tid < st) red[tid] += red[tid+st]; __syncthreads(); }
    if (tid == 0) g_pgen[row] = sigm(red[0] + bpg[0]);
}

// ---------------- split fp32 -> bf16 hi/lo ----------------
__global__ void k_cvtB(const float* __restrict__ Wp)
{
    size_t i = ((size_t)blockIdx.x*256 + threadIdx.x)*8;
    if (i >= (size_t)NPAD*G4) return;
    __nv_bfloat16 hi8[8], lo8[8];
    if (i < (size_t)VV*G4){
        float4 a = *(const float4*)(Wp + i);
        float4 b = *(const float4*)(Wp + i + 4);
        float v[8] = {a.x,a.y,a.z,a.w,b.x,b.y,b.z,b.w};
        #pragma unroll
        for (int j=0;j<8;j++){
            __nv_bfloat16 hv = __float2bfloat16_rn(v[j]);
            hi8[j] = hv;
            lo8[j] = __float2bfloat16_rn(v[j] - __bfloat162float(hv));
        }
    } else {
        #pragma unroll
        for (int j=0;j<8;j++){ hi8[j] = __float2bfloat16_rn(0.f); lo8[j] = hi8[j]; }
    }
    ((uint4*)g_Bhi)[i/8] = *(const uint4*)hi8;
    ((uint4*)g_Blo)[i/8] = *(const uint4*)lo8;
}

__global__ void k_cvtA()
{
    size_t i = ((size_t)blockIdx.x*256 + threadIdx.x)*8;
    if (i >= (size_t)MPAD*G4) return;
    __nv_bfloat16 hi8[8], lo8[8];
    if (i < (size_t)NROW*G4){
        float4 a = *(const float4*)(g_feat + i);
        float4 b = *(const float4*)(g_feat + i + 4);
        float v[8] = {a.x,a.y,a.z,a.w,b.x,b.y,b.z,b.w};
        #pragma unroll
        for (int j=0;j<8;j++){
            __nv_bfloat16 hv = __float2bfloat16_rn(v[j]);
            hi8[j] = hv;
            lo8[j] = __float2bfloat16_rn(v[j] - __bfloat162float(hv));
        }
    } else {
        #pragma unroll
        for (int j=0;j<8;j++){ hi8[j] = __float2bfloat16_rn(0.f); lo8[j] = hi8[j]; }
    }
    ((uint4*)g_Ahi)[i/8] = *(const uint4*)hi8;
    ((uint4*)g_Alo)[i/8] = *(const uint4*)lo8;
}

// ---------------- projection GEMM via wmma bf16 hi/lo split ----------------
__global__ void __launch_bounds__(256) k_wmma(float* __restrict__ out)
{
    __shared__ __align__(16) __nv_bfloat16 Ah[2][128*LDT];
    __shared__ __align__(16) __nv_bfloat16 Al[2][128*LDT];
    __shared__ __align__(16) __nv_bfloat16 Bh[2][64*LDT];
    __shared__ __align__(16) __nv_bfloat16 Bl[2][64*LDT];

    int tid = threadIdx.x, w = tid >> 5;
    int n0 = blockIdx.x*64, m0 = blockIdx.y*128;
    int wm = (w & 3) * 32, wn = (w >> 2) * 32;

    wmma::fragment<wmma::accumulator,16,16,16,float> cf[2][2];
    #pragma unroll
    for (int i=0;i<2;i++)
        #pragma unroll
        for (int j=0;j<2;j++) wmma::fill_fragment(cf[i][j], 0.f);

    int ar = tid >> 1, ak = (tid & 1) * 8;
    int br = (tid & 127) >> 1, bk = (tid & 1) * 8;
    bool isBh = tid < 128;
    const __nv_bfloat16* Bsrc = isBh ? g_Bhi : g_Blo;

    uint4 pah, pal, pbx;
    pah = *(const uint4*)(g_Ahi + (size_t)(m0+ar)*G4 + ak);
    pal = *(const uint4*)(g_Alo + (size_t)(m0+ar)*G4 + ak);
    pbx = *(const uint4*)(Bsrc + (size_t)(n0+br)*G4 + bk);
    *(uint4*)(&Ah[0][ar*LDT + ak]) = pah;
    *(uint4*)(&Al[0][ar*LDT + ak]) = pal;
    if (isBh) *(uint4*)(&Bh[0][br*LDT + bk]) = pbx;
    else      *(uint4*)(&Bl[0][br*LDT + bk]) = pbx;
    __syncthreads();

    for (int kc = 0; kc < 64; kc++){
        int cur = kc & 1, nxt = cur ^ 1;
        if (kc + 1 < 64){
            int ko = (kc+1)*16;
            pah = *(const uint4*)(g_Ahi + (size_t)(m0+ar)*G4 + ko + ak);
            pal = *(const uint4*)(g_Alo + (size_t)(m0+ar)*G4 + ko + ak);
            pbx = *(const uint4*)(Bsrc + (size_t)(n0+br)*G4 + ko + bk);
        }
        wmma::fragment<wmma::matrix_a,16,16,16,__nv_bfloat16,wmma::row_major> fah[2], fal[2];
        wmma::fragment<wmma::matrix_b,16,16,16,__nv_bfloat16,wmma::col_major> fbh[2], fbl[2];
        #pragma unroll
        for (int i=0;i<2;i++){
            wmma::load_matrix_sync(fah[i], &Ah[cur][(wm + i*16)*LDT], LDT);
            wmma::load_matrix_sync(fal[i], &Al[cur][(wm + i*16)*LDT], LDT);
            wmma::load_matrix_sync(fbh[i], &Bh[cur][(wn + i*16)*LDT], LDT);
            wmma::load_matrix_sync(fbl[i], &Bl[cur][(wn + i*16)*LDT], LDT);
        }
        #pragma unroll
        for (int i=0;i<2;i++)
            #pragma unroll
            for (int j=0;j<2;j++){
                wmma::mma_sync(cf[i][j], fah[i], fbh[j], cf[i][j]);
                wmma::mma_sync(cf[i][j], fah[i], fbl[j], cf[i][j]);
                wmma::mma_sync(cf[i][j], fal[i], fbh[j], cf[i][j]);
            }
        if (kc + 1 < 64){
            *(uint4*)(&Ah[nxt][ar*LDT + ak]) = pah;
            *(uint4*)(&Al[nxt][ar*LDT + ak]) = pal;
            if (isBh) *(uint4*)(&Bh[nxt][br*LDT + bk]) = pbx;
            else      *(uint4*)(&Bl[nxt][br*LDT + bk]) = pbx;
        }
        __syncthreads();
    }

    #pragma unroll
    for (int i=0;i<2;i++){
        int gm = m0 + wm + i*16;
        if (gm + 16 <= NROW){
            #pragma unroll
            for (int j=0;j<2;j++){
                int gn = n0 + wn + j*16;
                if (gn + 16 <= VV)
                    wmma::store_matrix_sync(out + (size_t)gm*VV + gn, cf[i][j], VV, wmma::mem_row_major);
            }
        }
    }
}

// ---------------- row softmax stats (bias folded in) ----------------
__global__ void __launch_bounds__(256) k_rowstats(const float* __restrict__ out, const float* __restrict__ bp)
{
    int row = blockIdx.x, tid = threadIdx.x;
    __shared__ float red[256];
    const float* r = out + (size_t)row*VV;
    float m = -1e30f;
    for (int i = tid; i < VV; i += 256) m = fmaxf(m, r[i] + bp[i]);
    red[tid] = m; __syncthreads();
    for (int st=128; st>0; st>>=1){ if (tid < st) red[tid] = fmaxf(red[tid], red[tid+st]); __syncthreads(); }
    m = red[0]; __syncthreads();
    float s = 0.f;
    for (int i = tid; i < VV; i += 256) s += __expf(r[i] + bp[i] - m);
    red[tid] = s; __syncthreads();
    for (int st=128; st>0; st>>=1){ if (tid < st) red[tid] += red[tid+st]; __syncthreads(); }
    if (tid == 0){
        g_rmax[row] = m;
        g_rscale[row] = g_pgen[row] / red[0];
    }
}

// ---------------- transform ----------------
__global__ void k_transform(float* __restrict__ out, const float* __restrict__ bp)
{
    int row = blockIdx.y;
    int p = blockIdx.x*256 + threadIdx.x;
    if (p >= VV/4) return;
    float m = g_rmax[row], sc = g_rscale[row];
    float4* o4 = (float4*)(out + (size_t)row*VV);
    float4 v = o4[p];
    float4 bb = ((const float4*)bp)[p];
    v.x = sc*__expf(v.x + bb.x - m) + EPSF;
    v.y = sc*__expf(v.y + bb.y - m) + EPSF;
    v.z = sc*__expf(v.z + bb.z - m) + EPSF;
    v.w = sc*__expf(v.w + bb.w - m) + EPSF;
    o4[p] = v;
}

// ---------------- pointer scatter ----------------
__global__ void k_scatter(const int* __restrict__ x, float* __restrict__ out)
{
    int row = blockIdx.x, s = threadIdx.x;
    if (s >= SIN) return;
    int b = row / SOUT;
    float w = (1.f - g_pgen[row]) * g_attn[(size_t)row*SIN + s];
    atomicAdd(out + (size_t)row*VV + x[b*SIN + s], w);
}

// ---------------- final log ----------------
__global__ void k_log(float* __restrict__ out)
{
    int row = blockIdx.y;
    int p = blockIdx.x*256 + threadIdx.x;
    if (p >= VV/4) return;
    float4* o4 = (float4*)(out + (size_t)row*VV);
    float4 v = o4[p];
    v.x = __logf(v.x); v.y = __logf(v.y); v.z = __logf(v.z); v.w = __logf(v.w);
    o4[p] = v;
}

extern "C" void kernel_launch(void* const* d_in, const int* in_sizes, int n_in,
                              void* d_out, int out_size)
{
    const int*   x    = (const int*)  d_in[0];
    const int*   ans  = (const int*)  d_in[1];
    const float* emb  = (const float*)d_in[2];
    const float* wif  = (const float*)d_in[3];
    const float* ehf  = (const float*)d_in[4];
    const float* ebf  = (const float*)d_in[5];
    const float* wib  = (const float*)d_in[6];
    const float* ehb  = (const float*)d_in[7];
    const float* ebb  = (const float*)d_in[8];
    const float* wid_ = (const float*)d_in[9];
    const float* dwh  = (const float*)d_in[10];
    const float* db   = (const float*)d_in[11];
    const float* Wp   = (const float*)d_in[12];
    const float* bp   = (const float*)d_in[13];
    const float* wpg  = (const float*)d_in[14];
    const float* bpg  = (const float*)d_in[15];
    float* out = (float*)d_out;

    float* xgf; cudaGetSymbolAddress((void**)&xgf, g_xgf);
    float* xgb; cudaGetSymbolAddress((void**)&xgb, g_xgb);
    float* xgd; cudaGetSymbolAddress((void**)&xgd, g_xgd);

    // order chosen so the profiled launch slot (4th) lands on k_enc2
    k_transpose<<<dim3(1024,3), 256>>>(ehf, ehb, dwh);
    k_xg_gemm<<<dim3(8, 50), 256>>>(emb, wif, ebf, x, SIN, 0, BB*SIN, xgf);
    k_xg_gemm<<<dim3(8, 50), 256>>>(emb, wib, ebb, x, SIN, 1, BB*SIN, xgb);
    k_enc2<<<64, 256>>>();
    k_xg_gemm<<<dim3(16, 13), 256>>>(emb, wid_, db, ans, SOUT, 0, BB*SOUT, xgd);
    k_ansemb<<<NROW, 32>>>(ans, emb);
    k_dec2<<<64, 256>>>();
    k_attn<<<NROW, 256>>>(wpg, bpg);
    k_cvtA<<<(int)(((size_t)MPAD*G4/8 + 255)/256), 256>>>();
    k_cvtB<<<(int)(((size_t)NPAD*G4/8 + 255)/256), 256>>>(Wp);
    k_wmma<<<dim3(NPAD/64, MPAD/128), 256>>>(out);
    k_rowstats<<<NROW, 256>>>(out, bp);
    k_transform<<<dim3((VV/4+255)/256, NROW), 256>>>(out, bp);
    k_scatter<<<NROW, 512>>>(x, out);
    k_log<<<dim3((VV/4+255)/256, NROW), 256>>>(out);
}